// round 15
// baseline (speedup 1.0000x reference)
#include <cuda_runtime.h>
#include <cuda_fp16.h>
#include <cstdint>
#include <math.h>

#define S_LEN 2048
#define BATCH 2
#define EMB   2048
#define NH    16
#define NKV   4
#define HD    128
#define KVDIM (NKV*HD)        // 512
#define KVS   (2*KVDIM)       // 1024
#define QKVN  (EMB + KVS)     // 3072
#define MROWS (BATCH*S_LEN)   // 4096

// ---------------- scratch (allocation-free) ----------------
__device__ __half g_x16[(size_t)MROWS * EMB];
__device__ __half g_w16[(size_t)QKVN * EMB];     // [Wq | Wk | Wv]
__device__ __half g_wo16[(size_t)EMB * EMB];
__device__ __half g_q16[(size_t)MROWS * EMB];
__device__ __half g_kv16[(size_t)MROWS * KVS];
__device__ __half g_a16[(size_t)MROWS * EMB];

// ---------------- common MMA helpers ----------------
__device__ __forceinline__ void ldsm_x4(uint32_t* r, uint32_t addr) {
    asm volatile("ldmatrix.sync.aligned.m8n8.x4.shared.b16 {%0,%1,%2,%3}, [%4];"
                 : "=r"(r[0]), "=r"(r[1]), "=r"(r[2]), "=r"(r[3]) : "r"(addr));
}
__device__ __forceinline__ void ldsm_x4_t(uint32_t* r, uint32_t addr) {
    asm volatile("ldmatrix.sync.aligned.m8n8.x4.trans.shared.b16 {%0,%1,%2,%3}, [%4];"
                 : "=r"(r[0]), "=r"(r[1]), "=r"(r[2]), "=r"(r[3]) : "r"(addr));
}
__device__ __forceinline__ void mma_16816(float* d, const uint32_t* a, uint32_t b0,
                                          uint32_t b1) {
    asm volatile(
        "mma.sync.aligned.m16n8k16.row.col.f32.f16.f16.f32 "
        "{%0,%1,%2,%3}, {%4,%5,%6,%7}, {%8,%9}, {%0,%1,%2,%3};"
        : "+f"(d[0]), "+f"(d[1]), "+f"(d[2]), "+f"(d[3])
        : "r"(a[0]), "r"(a[1]), "r"(a[2]), "r"(a[3]), "r"(b0), "r"(b1));
}
#define CPA16(dst, src) \
    asm volatile("cp.async.cg.shared.global [%0], [%1], 16;" :: "r"(dst), "l"(src))

__device__ __forceinline__ uint32_t pack_h2(float v0, float v1) {
    __half2 t;
    t.x = __float2half(v0); t.y = __float2half(v1);
    return *(uint32_t*)&t;
}
__device__ __forceinline__ float ex2(float x) {
    float r;
    asm("ex2.approx.f32 %0, %1;" : "=f"(r) : "f"(x));
    return r;
}

// ----------------------------------------------------------------------------
// ONE convert kernel: fp32 -> fp16 for all 5 inputs
// ----------------------------------------------------------------------------
#define UX   1048576
#define UWQ  (UX + 524288)
#define UWK  (UWQ + 131072)
#define UWV  (UWK + 131072)
#define UTOT (UWV + 524288)

__global__ __launch_bounds__(256) void conv_all(
    const float* __restrict__ x,  const float* __restrict__ Wq,
    const float* __restrict__ Wk, const float* __restrict__ Wv,
    const float* __restrict__ Wo)
{
    int i = blockIdx.x * blockDim.x + threadIdx.x;
    if (i >= UTOT) return;
    const float* src;
    __half* dst;
    size_t off;
    if (i < UX)        { src = x;  dst = g_x16;  off = (size_t)i; }
    else if (i < UWQ)  { src = Wq; dst = g_w16;  off = (size_t)(i - UX); }
    else if (i < UWK)  { src = Wk; dst = g_w16 + (size_t)EMB*EMB; off = (size_t)(i - UWQ); }
    else if (i < UWV)  { src = Wv; dst = g_w16 + (size_t)(EMB+KVDIM)*EMB; off = (size_t)(i - UWK); }
    else               { src = Wo; dst = g_wo16; off = (size_t)(i - UWV); }

    const float4* p = (const float4*)(src + off * 8);
    float4 a = p[0], b = p[1];
    uint32_t H[4];
    H[0] = pack_h2(a.x, a.y);
    H[1] = pack_h2(a.z, a.w);
    H[2] = pack_h2(b.x, b.y);
    H[3] = pack_h2(b.z, b.w);
    *(uint4*)(dst + off * 8) = make_uint4(H[0], H[1], H[2], H[3]);
}

// ----------------------------------------------------------------------------
// fp16 HMMA GEMM: BK=64, 3 stages x 32KB, single sync per k-iter. (unchanged)
// ----------------------------------------------------------------------------
#define GST 32768
#define GEMM_SMEM (3 * GST)

__device__ __forceinline__ uint32_t sw128g(int r, int c) {
    return (uint32_t)(r * 128 + ((c ^ (r & 7)) * 16));
}

__global__ __launch_bounds__(256, 2) void gemm_f16(
    const __half* __restrict__ A, const __half* __restrict__ B,
    float* __restrict__ Cf, int mode, float scale, int M, int N, int K)
{
    extern __shared__ __align__(1024) char smem[];
    const uint32_t sbase = (uint32_t)__cvta_generic_to_shared(smem);

    const int tid  = threadIdx.x;
    const int warp = tid >> 5, lane = tid & 31;
    const int wm   = warp & 3, wn = warp >> 2;
    const int brow = blockIdx.y * 128, bcol = blockIdx.x * 128;

    uint32_t dstA[4];
    const __half* sA[4];
    const __half* sB[4];
    #pragma unroll
    for (int it = 0; it < 4; it++) {
        int id  = it * 256 + tid;
        int row = id >> 3, c = id & 7;
        dstA[it] = sbase + sw128g(row, c);
        sA[it]   = A + (size_t)(brow + row) * K + c * 8;
        sB[it]   = B + (size_t)(bcol + row) * K + c * 8;
    }

    const int NT = K / 64;

    #define LOAD_STAGE(s, kt) do {                                             \
        uint32_t so = (uint32_t)(s) * GST;                                     \
        int ko = (kt) * 64;                                                    \
        _Pragma("unroll")                                                      \
        for (int it = 0; it < 4; it++) {                                       \
            CPA16(dstA[it] + so,         sA[it] + ko);                         \
            CPA16(dstA[it] + so + 16384, sB[it] + ko);                         \
        }                                                                      \
        asm volatile("cp.async.commit_group;");                                \
    } while (0)

    LOAD_STAGE(0, 0);
    LOAD_STAGE(1, 1);

    float acc[2][8][4];
    #pragma unroll
    for (int i = 0; i < 2; i++)
        #pragma unroll
        for (int j = 0; j < 8; j++)
            #pragma unroll
            for (int q = 0; q < 4; q++) acc[i][j][q] = 0.f;

    const int frow = lane & 15;
    const int fhi  = lane >> 4;

    for (int kt = 0; kt < NT; kt++) {
        int s = kt % 3;
        asm volatile("cp.async.wait_group 1;" ::: "memory");
        __syncthreads();
        if (kt + 2 < NT) { LOAD_STAGE((kt + 2) % 3, kt + 2); }
        else { asm volatile("cp.async.commit_group;"); }

        uint32_t ab = sbase + s * GST;

        #pragma unroll
        for (int ks = 0; ks < 4; ks++) {
            int c = ks * 2 + fhi;
            uint32_t ah[2][4];
            #pragma unroll
            for (int i = 0; i < 2; i++) {
                int row = wm * 32 + i * 16 + frow;
                ldsm_x4(ah[i], ab + sw128g(row, c));
            }
            #pragma unroll
            for (int g = 0; g < 4; g++) {
                uint32_t bh[4];
                int row = wn * 64 + g * 16 + frow;
                ldsm_x4(bh, ab + 16384 + sw128g(row, c));
                #pragma unroll
                for (int i = 0; i < 2; i++)
                    #pragma unroll
                    for (int p = 0; p < 2; p++)
                        mma_16816(acc[i][g*2+p], ah[i], bh[p], bh[p+2]);
            }
        }
    }

    const int erow = lane >> 2;
    const int ecol = (lane & 3) * 2;
    if (mode == 0) {
        #pragma unroll
        for (int i = 0; i < 2; i++) {
            int r0 = brow + wm * 32 + i * 16 + erow;
            #pragma unroll
            for (int j = 0; j < 8; j++) {
                int cc = bcol + wn * 64 + j * 8 + ecol;
                *(float2*)(Cf + (size_t)r0 * N + cc) =
                    make_float2(acc[i][j][0], acc[i][j][1]);
                *(float2*)(Cf + (size_t)(r0 + 8) * N + cc) =
                    make_float2(acc[i][j][2], acc[i][j][3]);
            }
        }
    } else {
        const bool isq = (bcol < EMB);
        const float sc = isq ? scale : 1.0f;
        #pragma unroll
        for (int i = 0; i < 2; i++) {
            int r0 = brow + wm * 32 + i * 16 + erow;
            #pragma unroll
            for (int j = 0; j < 8; j++) {
                int cc = bcol + wn * 64 + j * 8 + ecol;
                #pragma unroll
                for (int half = 0; half < 2; half++) {
                    int r = r0 + half * 8;
                    uint32_t H = pack_h2(acc[i][j][half*2] * sc,
                                         acc[i][j][half*2+1] * sc);
                    if (isq) {
                        *(uint32_t*)(g_q16 + (size_t)r * EMB + cc) = H;
                    } else {
                        *(uint32_t*)(g_kv16 + (size_t)r * KVS + (cc - EMB)) = H;
                    }
                }
            }
        }
    }
    #undef LOAD_STAGE
}

// ----------------------------------------------------------------------------
// fp16 FA2 flash attention: 64-row Q tile, 128 threads, K-prefetch double
// buffer, register softmax in exp2 domain (log2e folded into q scale).
// 4 CTAs/SM (48KB smem each).
// ----------------------------------------------------------------------------
#define AQ   0
#define AKV0 16384
#define AKV1 32768
#define ATT_SMEM 49152

__device__ __forceinline__ uint32_t sw256(int r, int c) {
    return (uint32_t)(r * 256 + (((c & 7) ^ (r & 7)) | (c & 8)) * 16);
}

__global__ __launch_bounds__(128, 4) void attn_mma()
{
    extern __shared__ __align__(1024) char smraw[];
    const uint32_t sb = (uint32_t)__cvta_generic_to_shared(smraw);

    const int tid  = threadIdx.x;
    const int wm   = tid >> 5, lane = tid & 31;
    const int frow = lane & 15, fhi = lane >> 4;
    const int q    = lane >> 2, tc = lane & 3;
    const int iq   = (int)(gridDim.x - 1 - blockIdx.x);   // longest first
    const int h    = blockIdx.y;
    const int b    = blockIdx.z;
    const int kvhead = h / (NH / NKV);

    const __half* kb = g_kv16 + ((size_t)(b * S_LEN)) * KVS + kvhead * HD;

    // ---- prologue: load Q and K(0) ----
    {
        const __half* qp = g_q16 + ((size_t)(b * S_LEN + iq * 64)) * EMB + h * HD;
        #pragma unroll
        for (int it = 0; it < 8; it++) {
            int id = it * 128 + tid;
            int r = id >> 4, c = id & 15;
            CPA16(sb + AQ + sw256(r, c), qp + (size_t)r * EMB + c * 8);
        }
        asm volatile("cp.async.commit_group;");
        const __half* kp = kb;   // jt = 0
        #pragma unroll
        for (int it = 0; it < 8; it++) {
            int id = it * 128 + tid;
            int r = id >> 4, c = id & 15;
            CPA16(sb + AKV0 + sw256(r, c), kp + (size_t)r * KVS + c * 8);
        }
        asm volatile("cp.async.commit_group;");
    }

    float o[16][4];
    #pragma unroll
    for (int j = 0; j < 16; j++)
        #pragma unroll
        for (int e = 0; e < 4; e++) o[j][e] = 0.f;
    float m0 = -3.0e38f, m1 = -3.0e38f, l0 = 0.f, l1 = 0.f;

    for (int jt = 0; jt <= iq; jt++) {
        const uint32_t bufA = sb + ((jt & 1) ? AKV1 : AKV0);
        const uint32_t bufB = sb + ((jt & 1) ? AKV0 : AKV1);

        asm volatile("cp.async.wait_group 0;" ::: "memory");
        __syncthreads();   // K(jt) ready in bufA; prev PV readers done with bufA

        // ---- QK^T (scores already in log2 domain via folded q scale) ----
        float sc[8][4];
        #pragma unroll
        for (int j = 0; j < 8; j++)
            #pragma unroll
            for (int e = 0; e < 4; e++) sc[j][e] = 0.f;

        #pragma unroll
        for (int ks = 0; ks < 8; ks++) {
            int c = ks * 2 + fhi;
            uint32_t ah[4];
            ldsm_x4(ah, sb + AQ + sw256(wm * 16 + frow, c));
            #pragma unroll
            for (int g = 0; g < 4; g++) {
                uint32_t bh[4];
                ldsm_x4(bh, bufA + sw256(g * 16 + frow, c));
                mma_16816(sc[g*2],   ah, bh[0], bh[2]);
                mma_16816(sc[g*2+1], ah, bh[1], bh[3]);
            }
        }
        __syncthreads();   // all warps done reading K from bufA

        // ---- issue V(jt) into bufA (overlaps softmax) ----
        {
            const __half* vp = kb + KVDIM + (size_t)(jt * 64) * KVS;
            #pragma unroll
            for (int it = 0; it < 8; it++) {
                int id = it * 128 + tid;
                int r = id >> 4, c = id & 15;
                CPA16(bufA + sw256(r, c), vp + (size_t)r * KVS + c * 8);
            }
            asm volatile("cp.async.commit_group;");
        }

        // ---- register softmax (exp2 domain) ----
        if (jt == iq) {
            int r0 = wm * 16 + q, r1 = r0 + 8;
            #pragma unroll
            for (int j = 0; j < 8; j++) {
                int c0 = j * 8 + tc * 2;
                if (c0     > r0) sc[j][0] = -3.0e38f;
                if (c0 + 1 > r0) sc[j][1] = -3.0e38f;
                if (c0     > r1) sc[j][2] = -3.0e38f;
                if (c0 + 1 > r1) sc[j][3] = -3.0e38f;
            }
        }
        float mx0 = sc[0][0], mx1 = sc[0][2];
        #pragma unroll
        for (int j = 0; j < 8; j++) {
            mx0 = fmaxf(mx0, fmaxf(sc[j][0], sc[j][1]));
            mx1 = fmaxf(mx1, fmaxf(sc[j][2], sc[j][3]));
        }
        mx0 = fmaxf(mx0, __shfl_xor_sync(0xFFFFFFFF, mx0, 1));
        mx0 = fmaxf(mx0, __shfl_xor_sync(0xFFFFFFFF, mx0, 2));
        mx1 = fmaxf(mx1, __shfl_xor_sync(0xFFFFFFFF, mx1, 1));
        mx1 = fmaxf(mx1, __shfl_xor_sync(0xFFFFFFFF, mx1, 2));
        float mn0 = fmaxf(m0, mx0), mn1 = fmaxf(m1, mx1);
        float cf0 = ex2(m0 - mn0), cf1 = ex2(m1 - mn1);
        float s0 = 0.f, s1 = 0.f;
        #pragma unroll
        for (int j = 0; j < 8; j++) {
            sc[j][0] = ex2(sc[j][0] - mn0); s0 += sc[j][0];
            sc[j][1] = ex2(sc[j][1] - mn0); s0 += sc[j][1];
            sc[j][2] = ex2(sc[j][2] - mn1); s1 += sc[j][2];
            sc[j][3] = ex2(sc[j][3] - mn1); s1 += sc[j][3];
        }
        s0 += __shfl_xor_sync(0xFFFFFFFF, s0, 1);
        s0 += __shfl_xor_sync(0xFFFFFFFF, s0, 2);
        s1 += __shfl_xor_sync(0xFFFFFFFF, s1, 1);
        s1 += __shfl_xor_sync(0xFFFFFFFF, s1, 2);
        l0 = l0 * cf0 + s0;  l1 = l1 * cf1 + s1;
        m0 = mn0;  m1 = mn1;

        #pragma unroll
        for (int j = 0; j < 16; j++) {
            o[j][0] *= cf0; o[j][1] *= cf0;
            o[j][2] *= cf1; o[j][3] *= cf1;
        }

        uint32_t ph[4][4];
        #pragma unroll
        for (int kc = 0; kc < 4; kc++) {
            ph[kc][0] = pack_h2(sc[kc*2][0],   sc[kc*2][1]);
            ph[kc][1] = pack_h2(sc[kc*2][2],   sc[kc*2][3]);
            ph[kc][2] = pack_h2(sc[kc*2+1][0], sc[kc*2+1][1]);
            ph[kc][3] = pack_h2(sc[kc*2+1][2], sc[kc*2+1][3]);
        }

        asm volatile("cp.async.wait_group 0;" ::: "memory");
        __syncthreads();   // V(jt) ready in bufA

        // ---- prefetch K(jt+1) into bufB (overlaps PV) ----
        if (jt < iq) {
            const __half* kp = kb + (size_t)((jt + 1) * 64) * KVS;
            #pragma unroll
            for (int it = 0; it < 8; it++) {
                int id = it * 128 + tid;
                int r = id >> 4, c = id & 15;
                CPA16(bufB + sw256(r, c), kp + (size_t)r * KVS + c * 8);
            }
        }
        asm volatile("cp.async.commit_group;");

        // ---- O += P @ V ----
        int t = ((lane >> 3) & 1) * 8 + (lane & 7);
        #pragma unroll
        for (int kc = 0; kc < 4; kc++) {
            #pragma unroll
            for (int g = 0; g < 8; g++) {
                int cd = g * 2 + fhi;
                uint32_t bv[4];
                ldsm_x4_t(bv, bufA + sw256(kc * 16 + t, cd));
                mma_16816(o[g*2],   ph[kc], bv[0], bv[1]);
                mma_16816(o[g*2+1], ph[kc], bv[2], bv[3]);
            }
        }
    }

    // ---- epilogue: normalize + fp16 write ----
    {
        float invl0 = 1.f / l0, invl1 = 1.f / l1;
        size_t base = ((size_t)(b * S_LEN + iq * 64 + wm * 16 + q)) * EMB + h * HD;
        #pragma unroll
        for (int j = 0; j < 16; j++) {
            int col = j * 8 + tc * 2;
            *(uint32_t*)(g_a16 + base + col) =
                pack_h2(o[j][0] * invl0, o[j][1] * invl0);
            *(uint32_t*)(g_a16 + base + 8*EMB + col) =
                pack_h2(o[j][2] * invl1, o[j][3] * invl1);
        }
    }
}

// ----------------------------------------------------------------------------
// Launch
// ----------------------------------------------------------------------------
extern "C" void kernel_launch(void* const* d_in, const int* in_sizes, int n_in,
                              void* d_out, int out_size)
{
    const float* x  = (const float*)d_in[0];
    const float* Wq = (const float*)d_in[1];
    const float* Wk = (const float*)d_in[2];
    const float* Wv = (const float*)d_in[3];
    const float* Wo = (const float*)d_in[4];
    float* out = (float*)d_out;

    __half *x16, *w16, *wo16, *a16;
    cudaGetSymbolAddress((void**)&x16, g_x16);
    cudaGetSymbolAddress((void**)&w16, g_w16);
    cudaGetSymbolAddress((void**)&wo16, g_wo16);
    cudaGetSymbolAddress((void**)&a16, g_a16);

    cudaFuncSetAttribute(gemm_f16, cudaFuncAttributeMaxDynamicSharedMemorySize, GEMM_SMEM);
    cudaFuncSetAttribute(attn_mma, cudaFuncAttributeMaxDynamicSharedMemorySize, ATT_SMEM);

    conv_all<<<(UTOT + 255) / 256, 256>>>(x, Wq, Wk, Wv, Wo);

    // 1/sqrt(128) * log2(e): scores come out of QK^T already in log2 domain
    const float qscale = (float)(0.08838834764831845 * 1.4426950408889634);

    dim3 gqkv(QKVN / 128, MROWS / 128);   // (24, 32)
    gemm_f16<<<gqkv, 256, GEMM_SMEM>>>(x16, w16, nullptr, 1, qscale,
                                       MROWS, QKVN, EMB);

    dim3 ga(S_LEN / 64, NH, BATCH);       // (32, 16, 2)
    attn_mma<<<ga, 128, ATT_SMEM>>>();

    dim3 go(EMB / 128, MROWS / 128);      // (16, 32)
    gemm_f16<<<go, 256, GEMM_SMEM>>>(a16, wo16, out, 0, 1.0f,
                                     MROWS, EMB, EMB);
}

// round 16
// speedup vs baseline: 1.0771x; 1.0771x over previous
#include <cuda_runtime.h>
#include <cuda_fp16.h>
#include <cstdint>
#include <math.h>

#define S_LEN 2048
#define BATCH 2
#define EMB   2048
#define NH    16
#define NKV   4
#define HD    128
#define KVDIM (NKV*HD)        // 512
#define KVS   (2*KVDIM)       // 1024
#define QKVN  (EMB + KVS)     // 3072
#define MROWS (BATCH*S_LEN)   // 4096

// ---------------- scratch (allocation-free) ----------------
__device__ __half g_x16[(size_t)MROWS * EMB];
__device__ __half g_w16[(size_t)QKVN * EMB];     // [Wq | Wk | Wv]
__device__ __half g_wo16[(size_t)EMB * EMB];
__device__ __half g_q16[(size_t)MROWS * EMB];
__device__ __half g_kv16[(size_t)MROWS * KVS];
__device__ __half g_a16[(size_t)MROWS * EMB];

// ---------------- common MMA helpers ----------------
__device__ __forceinline__ void ldsm_x4(uint32_t* r, uint32_t addr) {
    asm volatile("ldmatrix.sync.aligned.m8n8.x4.shared.b16 {%0,%1,%2,%3}, [%4];"
                 : "=r"(r[0]), "=r"(r[1]), "=r"(r[2]), "=r"(r[3]) : "r"(addr));
}
__device__ __forceinline__ void ldsm_x4_t(uint32_t* r, uint32_t addr) {
    asm volatile("ldmatrix.sync.aligned.m8n8.x4.trans.shared.b16 {%0,%1,%2,%3}, [%4];"
                 : "=r"(r[0]), "=r"(r[1]), "=r"(r[2]), "=r"(r[3]) : "r"(addr));
}
__device__ __forceinline__ void mma_16816(float* d, const uint32_t* a, uint32_t b0,
                                          uint32_t b1) {
    asm volatile(
        "mma.sync.aligned.m16n8k16.row.col.f32.f16.f16.f32 "
        "{%0,%1,%2,%3}, {%4,%5,%6,%7}, {%8,%9}, {%0,%1,%2,%3};"
        : "+f"(d[0]), "+f"(d[1]), "+f"(d[2]), "+f"(d[3])
        : "r"(a[0]), "r"(a[1]), "r"(a[2]), "r"(a[3]), "r"(b0), "r"(b1));
}
#define CPA16(dst, src) \
    asm volatile("cp.async.cg.shared.global [%0], [%1], 16;" :: "r"(dst), "l"(src))

__device__ __forceinline__ uint32_t pack_h2(float v0, float v1) {
    __half2 t;
    t.x = __float2half(v0); t.y = __float2half(v1);
    return *(uint32_t*)&t;
}
__device__ __forceinline__ float ex2(float x) {
    float r;
    asm("ex2.approx.f32 %0, %1;" : "=f"(r) : "f"(x));
    return r;
}

// ----------------------------------------------------------------------------
// ONE convert kernel: fp32 -> fp16 for all 5 inputs
// ----------------------------------------------------------------------------
#define UX   1048576
#define UWQ  (UX + 524288)
#define UWK  (UWQ + 131072)
#define UWV  (UWK + 131072)
#define UTOT (UWV + 524288)

__global__ __launch_bounds__(256) void conv_all(
    const float* __restrict__ x,  const float* __restrict__ Wq,
    const float* __restrict__ Wk, const float* __restrict__ Wv,
    const float* __restrict__ Wo)
{
    int i = blockIdx.x * blockDim.x + threadIdx.x;
    if (i >= UTOT) return;
    const float* src;
    __half* dst;
    size_t off;
    if (i < UX)        { src = x;  dst = g_x16;  off = (size_t)i; }
    else if (i < UWQ)  { src = Wq; dst = g_w16;  off = (size_t)(i - UX); }
    else if (i < UWK)  { src = Wk; dst = g_w16 + (size_t)EMB*EMB; off = (size_t)(i - UWQ); }
    else if (i < UWV)  { src = Wv; dst = g_w16 + (size_t)(EMB+KVDIM)*EMB; off = (size_t)(i - UWK); }
    else               { src = Wo; dst = g_wo16; off = (size_t)(i - UWV); }

    const float4* p = (const float4*)(src + off * 8);
    float4 a = p[0], b = p[1];
    uint32_t H[4];
    H[0] = pack_h2(a.x, a.y);
    H[1] = pack_h2(a.z, a.w);
    H[2] = pack_h2(b.x, b.y);
    H[3] = pack_h2(b.z, b.w);
    *(uint4*)(dst + off * 8) = make_uint4(H[0], H[1], H[2], H[3]);
}

// ----------------------------------------------------------------------------
// fp16 HMMA GEMM: BK=64, 3 stages x 32KB, single sync per k-iter. (unchanged)
// ----------------------------------------------------------------------------
#define GST 32768
#define GEMM_SMEM (3 * GST)

__device__ __forceinline__ uint32_t sw128g(int r, int c) {
    return (uint32_t)(r * 128 + ((c ^ (r & 7)) * 16));
}

__global__ __launch_bounds__(256, 2) void gemm_f16(
    const __half* __restrict__ A, const __half* __restrict__ B,
    float* __restrict__ Cf, int mode, float scale, int M, int N, int K)
{
    extern __shared__ __align__(1024) char smem[];
    const uint32_t sbase = (uint32_t)__cvta_generic_to_shared(smem);

    const int tid  = threadIdx.x;
    const int warp = tid >> 5, lane = tid & 31;
    const int wm   = warp & 3, wn = warp >> 2;
    const int brow = blockIdx.y * 128, bcol = blockIdx.x * 128;

    uint32_t dstA[4];
    const __half* sA[4];
    const __half* sB[4];
    #pragma unroll
    for (int it = 0; it < 4; it++) {
        int id  = it * 256 + tid;
        int row = id >> 3, c = id & 7;
        dstA[it] = sbase + sw128g(row, c);
        sA[it]   = A + (size_t)(brow + row) * K + c * 8;
        sB[it]   = B + (size_t)(bcol + row) * K + c * 8;
    }

    const int NT = K / 64;

    #define LOAD_STAGE(s, kt) do {                                             \
        uint32_t so = (uint32_t)(s) * GST;                                     \
        int ko = (kt) * 64;                                                    \
        _Pragma("unroll")                                                      \
        for (int it = 0; it < 4; it++) {                                       \
            CPA16(dstA[it] + so,         sA[it] + ko);                         \
            CPA16(dstA[it] + so + 16384, sB[it] + ko);                         \
        }                                                                      \
        asm volatile("cp.async.commit_group;");                                \
    } while (0)

    LOAD_STAGE(0, 0);
    LOAD_STAGE(1, 1);

    float acc[2][8][4];
    #pragma unroll
    for (int i = 0; i < 2; i++)
        #pragma unroll
        for (int j = 0; j < 8; j++)
            #pragma unroll
            for (int q = 0; q < 4; q++) acc[i][j][q] = 0.f;

    const int frow = lane & 15;
    const int fhi  = lane >> 4;

    for (int kt = 0; kt < NT; kt++) {
        int s = kt % 3;
        asm volatile("cp.async.wait_group 1;" ::: "memory");
        __syncthreads();
        if (kt + 2 < NT) { LOAD_STAGE((kt + 2) % 3, kt + 2); }
        else { asm volatile("cp.async.commit_group;"); }

        uint32_t ab = sbase + s * GST;

        #pragma unroll
        for (int ks = 0; ks < 4; ks++) {
            int c = ks * 2 + fhi;
            uint32_t ah[2][4];
            #pragma unroll
            for (int i = 0; i < 2; i++) {
                int row = wm * 32 + i * 16 + frow;
                ldsm_x4(ah[i], ab + sw128g(row, c));
            }
            #pragma unroll
            for (int g = 0; g < 4; g++) {
                uint32_t bh[4];
                int row = wn * 64 + g * 16 + frow;
                ldsm_x4(bh, ab + 16384 + sw128g(row, c));
                #pragma unroll
                for (int i = 0; i < 2; i++)
                    #pragma unroll
                    for (int p = 0; p < 2; p++)
                        mma_16816(acc[i][g*2+p], ah[i], bh[p], bh[p+2]);
            }
        }
    }

    const int erow = lane >> 2;
    const int ecol = (lane & 3) * 2;
    if (mode == 0) {
        #pragma unroll
        for (int i = 0; i < 2; i++) {
            int r0 = brow + wm * 32 + i * 16 + erow;
            #pragma unroll
            for (int j = 0; j < 8; j++) {
                int cc = bcol + wn * 64 + j * 8 + ecol;
                *(float2*)(Cf + (size_t)r0 * N + cc) =
                    make_float2(acc[i][j][0], acc[i][j][1]);
                *(float2*)(Cf + (size_t)(r0 + 8) * N + cc) =
                    make_float2(acc[i][j][2], acc[i][j][3]);
            }
        }
    } else {
        const bool isq = (bcol < EMB);
        const float sc = isq ? scale : 1.0f;
        #pragma unroll
        for (int i = 0; i < 2; i++) {
            int r0 = brow + wm * 32 + i * 16 + erow;
            #pragma unroll
            for (int j = 0; j < 8; j++) {
                int cc = bcol + wn * 64 + j * 8 + ecol;
                #pragma unroll
                for (int half = 0; half < 2; half++) {
                    int r = r0 + half * 8;
                    uint32_t H = pack_h2(acc[i][j][half*2] * sc,
                                         acc[i][j][half*2+1] * sc);
                    if (isq) {
                        *(uint32_t*)(g_q16 + (size_t)r * EMB + cc) = H;
                    } else {
                        *(uint32_t*)(g_kv16 + (size_t)r * KVS + (cc - EMB)) = H;
                    }
                }
            }
        }
    }
    #undef LOAD_STAGE
}

// ----------------------------------------------------------------------------
// fp16 FA2 flash attention: 64-row Q tile, 128 threads, 3 CTAs/SM (known-good
// R12/R14 shape), K-prefetch double buffer, softmax in exp2 domain (ONLY
// delta vs R14: log2e folded into q scale, ex2.approx in softmax).
// ----------------------------------------------------------------------------
#define AQ   0
#define AKV0 16384
#define AKV1 32768
#define ATT_SMEM 49152

__device__ __forceinline__ uint32_t sw256(int r, int c) {
    return (uint32_t)(r * 256 + (((c & 7) ^ (r & 7)) | (c & 8)) * 16);
}

__global__ __launch_bounds__(128, 3) void attn_mma()
{
    extern __shared__ __align__(1024) char smraw[];
    const uint32_t sb = (uint32_t)__cvta_generic_to_shared(smraw);

    const int tid  = threadIdx.x;
    const int wm   = tid >> 5, lane = tid & 31;
    const int frow = lane & 15, fhi = lane >> 4;
    const int q    = lane >> 2, tc = lane & 3;
    const int iq   = (int)(gridDim.x - 1 - blockIdx.x);   // longest first
    const int h    = blockIdx.y;
    const int b    = blockIdx.z;
    const int kvhead = h / (NH / NKV);

    const __half* kb = g_kv16 + ((size_t)(b * S_LEN)) * KVS + kvhead * HD;

    // ---- prologue: load Q and K(0) ----
    {
        const __half* qp = g_q16 + ((size_t)(b * S_LEN + iq * 64)) * EMB + h * HD;
        #pragma unroll
        for (int it = 0; it < 8; it++) {
            int id = it * 128 + tid;
            int r = id >> 4, c = id & 15;
            CPA16(sb + AQ + sw256(r, c), qp + (size_t)r * EMB + c * 8);
        }
        asm volatile("cp.async.commit_group;");
        const __half* kp = kb;   // jt = 0
        #pragma unroll
        for (int it = 0; it < 8; it++) {
            int id = it * 128 + tid;
            int r = id >> 4, c = id & 15;
            CPA16(sb + AKV0 + sw256(r, c), kp + (size_t)r * KVS + c * 8);
        }
        asm volatile("cp.async.commit_group;");
    }

    float o[16][4];
    #pragma unroll
    for (int j = 0; j < 16; j++)
        #pragma unroll
        for (int e = 0; e < 4; e++) o[j][e] = 0.f;
    float m0 = -3.0e38f, m1 = -3.0e38f, l0 = 0.f, l1 = 0.f;

    for (int jt = 0; jt <= iq; jt++) {
        const uint32_t bufA = sb + ((jt & 1) ? AKV1 : AKV0);
        const uint32_t bufB = sb + ((jt & 1) ? AKV0 : AKV1);

        asm volatile("cp.async.wait_group 0;" ::: "memory");
        __syncthreads();   // K(jt) ready in bufA; prev PV readers done with bufA

        // ---- QK^T (scores in log2 domain via folded q scale) ----
        float sc[8][4];
        #pragma unroll
        for (int j = 0; j < 8; j++)
            #pragma unroll
            for (int e = 0; e < 4; e++) sc[j][e] = 0.f;

        #pragma unroll
        for (int ks = 0; ks < 8; ks++) {
            int c = ks * 2 + fhi;
            uint32_t ah[4];
            ldsm_x4(ah, sb + AQ + sw256(wm * 16 + frow, c));
            #pragma unroll
            for (int g = 0; g < 4; g++) {
                uint32_t bh[4];
                ldsm_x4(bh, bufA + sw256(g * 16 + frow, c));
                mma_16816(sc[g*2],   ah, bh[0], bh[2]);
                mma_16816(sc[g*2+1], ah, bh[1], bh[3]);
            }
        }
        __syncthreads();   // all warps done reading K from bufA

        // ---- issue V(jt) into bufA (overlaps softmax) ----
        {
            const __half* vp = kb + KVDIM + (size_t)(jt * 64) * KVS;
            #pragma unroll
            for (int it = 0; it < 8; it++) {
                int id = it * 128 + tid;
                int r = id >> 4, c = id & 15;
                CPA16(bufA + sw256(r, c), vp + (size_t)r * KVS + c * 8);
            }
            asm volatile("cp.async.commit_group;");
        }

        // ---- register softmax (exp2 domain) ----
        if (jt == iq) {
            int r0 = wm * 16 + q, r1 = r0 + 8;
            #pragma unroll
            for (int j = 0; j < 8; j++) {
                int c0 = j * 8 + tc * 2;
                if (c0     > r0) sc[j][0] = -3.0e38f;
                if (c0 + 1 > r0) sc[j][1] = -3.0e38f;
                if (c0     > r1) sc[j][2] = -3.0e38f;
                if (c0 + 1 > r1) sc[j][3] = -3.0e38f;
            }
        }
        float mx0 = sc[0][0], mx1 = sc[0][2];
        #pragma unroll
        for (int j = 0; j < 8; j++) {
            mx0 = fmaxf(mx0, fmaxf(sc[j][0], sc[j][1]));
            mx1 = fmaxf(mx1, fmaxf(sc[j][2], sc[j][3]));
        }
        mx0 = fmaxf(mx0, __shfl_xor_sync(0xFFFFFFFF, mx0, 1));
        mx0 = fmaxf(mx0, __shfl_xor_sync(0xFFFFFFFF, mx0, 2));
        mx1 = fmaxf(mx1, __shfl_xor_sync(0xFFFFFFFF, mx1, 1));
        mx1 = fmaxf(mx1, __shfl_xor_sync(0xFFFFFFFF, mx1, 2));
        float mn0 = fmaxf(m0, mx0), mn1 = fmaxf(m1, mx1);
        float cf0 = ex2(m0 - mn0), cf1 = ex2(m1 - mn1);
        float s0 = 0.f, s1 = 0.f;
        #pragma unroll
        for (int j = 0; j < 8; j++) {
            sc[j][0] = ex2(sc[j][0] - mn0); s0 += sc[j][0];
            sc[j][1] = ex2(sc[j][1] - mn0); s0 += sc[j][1];
            sc[j][2] = ex2(sc[j][2] - mn1); s1 += sc[j][2];
            sc[j][3] = ex2(sc[j][3] - mn1); s1 += sc[j][3];
        }
        s0 += __shfl_xor_sync(0xFFFFFFFF, s0, 1);
        s0 += __shfl_xor_sync(0xFFFFFFFF, s0, 2);
        s1 += __shfl_xor_sync(0xFFFFFFFF, s1, 1);
        s1 += __shfl_xor_sync(0xFFFFFFFF, s1, 2);
        l0 = l0 * cf0 + s0;  l1 = l1 * cf1 + s1;
        m0 = mn0;  m1 = mn1;

        #pragma unroll
        for (int j = 0; j < 16; j++) {
            o[j][0] *= cf0; o[j][1] *= cf0;
            o[j][2] *= cf1; o[j][3] *= cf1;
        }

        uint32_t ph[4][4];
        #pragma unroll
        for (int kc = 0; kc < 4; kc++) {
            ph[kc][0] = pack_h2(sc[kc*2][0],   sc[kc*2][1]);
            ph[kc][1] = pack_h2(sc[kc*2][2],   sc[kc*2][3]);
            ph[kc][2] = pack_h2(sc[kc*2+1][0], sc[kc*2+1][1]);
            ph[kc][3] = pack_h2(sc[kc*2+1][2], sc[kc*2+1][3]);
        }

        asm volatile("cp.async.wait_group 0;" ::: "memory");
        __syncthreads();   // V(jt) ready in bufA

        // ---- prefetch K(jt+1) into bufB (overlaps PV) ----
        if (jt < iq) {
            const __half* kp = kb + (size_t)((jt + 1) * 64) * KVS;
            #pragma unroll
            for (int it = 0; it < 8; it++) {
                int id = it * 128 + tid;
                int r = id >> 4, c = id & 15;
                CPA16(bufB + sw256(r, c), kp + (size_t)r * KVS + c * 8);
            }
        }
        asm volatile("cp.async.commit_group;");

        // ---- O += P @ V ----
        int t = ((lane >> 3) & 1) * 8 + (lane & 7);
        #pragma unroll
        for (int kc = 0; kc < 4; kc++) {
            #pragma unroll
            for (int g = 0; g < 8; g++) {
                int cd = g * 2 + fhi;
                uint32_t bv[4];
                ldsm_x4_t(bv, bufA + sw256(kc * 16 + t, cd));
                mma_16816(o[g*2],   ph[kc], bv[0], bv[1]);
                mma_16816(o[g*2+1], ph[kc], bv[2], bv[3]);
            }
        }
    }

    // ---- epilogue: normalize + fp16 write ----
    {
        float invl0 = 1.f / l0, invl1 = 1.f / l1;
        size_t base = ((size_t)(b * S_LEN + iq * 64 + wm * 16 + q)) * EMB + h * HD;
        #pragma unroll
        for (int j = 0; j < 16; j++) {
            int col = j * 8 + tc * 2;
            *(uint32_t*)(g_a16 + base + col) =
                pack_h2(o[j][0] * invl0, o[j][1] * invl0);
            *(uint32_t*)(g_a16 + base + 8*EMB + col) =
                pack_h2(o[j][2] * invl1, o[j][3] * invl1);
        }
    }
}

// ----------------------------------------------------------------------------
// Launch
// ----------------------------------------------------------------------------
extern "C" void kernel_launch(void* const* d_in, const int* in_sizes, int n_in,
                              void* d_out, int out_size)
{
    const float* x  = (const float*)d_in[0];
    const float* Wq = (const float*)d_in[1];
    const float* Wk = (const float*)d_in[2];
    const float* Wv = (const float*)d_in[3];
    const float* Wo = (const float*)d_in[4];
    float* out = (float*)d_out;

    __half *x16, *w16, *wo16, *a16;
    cudaGetSymbolAddress((void**)&x16, g_x16);
    cudaGetSymbolAddress((void**)&w16, g_w16);
    cudaGetSymbolAddress((void**)&wo16, g_wo16);
    cudaGetSymbolAddress((void**)&a16, g_a16);

    cudaFuncSetAttribute(gemm_f16, cudaFuncAttributeMaxDynamicSharedMemorySize, GEMM_SMEM);
    cudaFuncSetAttribute(attn_mma, cudaFuncAttributeMaxDynamicSharedMemorySize, ATT_SMEM);

    conv_all<<<(UTOT + 255) / 256, 256>>>(x, Wq, Wk, Wv, Wo);

    // 1/sqrt(128) * log2(e): scores come out of QK^T already in log2 domain
    const float qscale = (float)(0.08838834764831845 * 1.4426950408889634);

    dim3 gqkv(QKVN / 128, MROWS / 128);   // (24, 32)
    gemm_f16<<<gqkv, 256, GEMM_SMEM>>>(x16, w16, nullptr, 1, qscale,
                                       MROWS, QKVN, EMB);

    dim3 ga(S_LEN / 64, NH, BATCH);       // (32, 16, 2)
    attn_mma<<<ga, 128, ATT_SMEM>>>();

    dim3 go(EMB / 128, MROWS / 128);      // (16, 32)
    gemm_f16<<<go, 256, GEMM_SMEM>>>(a16, wo16, out, 0, 1.0f,
                                     MROWS, EMB, EMB);
}